// round 3
// baseline (speedup 1.0000x reference)
#include <cuda_runtime.h>
#include <math.h>

#define NW    19
#define NH    19
#define NPIX  361          // 19*19
#define NA_   5
#define NCH   26           // 13 + NC
#define TOTCH 130          // NA_*NCH
#define MAXB  64
#define MAXOBJ 50
#define NANCH (NA_*NPIX)   // 1805
#define TSTRIDE 750        // MAXOBJ*15

// 1/(6*(e^2-1))  and 1/(e^2-1)
#define INV6CONF0 0.026086274f
#define INVCONF0  0.15651764f

// scratch (no allocations allowed)
__device__ double        g_acc;
__device__ float         g_tconf[MAXB * NPIX];
__device__ float         g_tvals[MAXB * NPIX * 12];
__device__ int           g_tcls [MAXB * NPIX];
__device__ unsigned char g_flag [MAXB * NPIX];

__device__ __forceinline__ float sigmoidf_(float x) {
    return 1.0f / (1.0f + __expf(-x));
}

__device__ __forceinline__ void block_reduce_add(float v) {
    #pragma unroll
    for (int o = 16; o > 0; o >>= 1) v += __shfl_down_sync(0xffffffffu, v, o);
    __shared__ float ws[32];
    int lane = threadIdx.x & 31, w = threadIdx.x >> 5;
    if (lane == 0) ws[w] = v;
    __syncthreads();
    if (w == 0) {
        int nw = (blockDim.x + 31) >> 5;
        float x = (lane < nw) ? ws[lane] : 0.0f;
        #pragma unroll
        for (int o = 16; o > 0; o >>= 1) x += __shfl_down_sync(0xffffffffu, x, o);
        if (lane == 0) atomicAdd(&g_acc, (double)x);
    }
}

__global__ void k_zero() { g_acc = 0.0; }

// -------------------------------------------------------------------------
// Per-cell gather of the scatter-with-overwrite scan:
// last valid object t whose (gj*19+gi)==cell wins. Writes flag/tvals/tcls and
// tconf = confs[b, t_win, cell] (anchor 0 pred corners at that pixel).
// grid = nB blocks, 384 threads (361 active cells).
// -------------------------------------------------------------------------
__global__ void k_assign(const float* __restrict__ out, const float* __restrict__ tgt) {
    int b = blockIdx.x;
    int c = threadIdx.x;
    __shared__ float sg[MAXOBJ][12];
    __shared__ int s_nv;

    for (int idx = threadIdx.x; idx < MAXOBJ * 12; idx += blockDim.x) {
        int t = idx / 12, m = idx - t * 12;
        sg[t][m] = tgt[b * TSTRIDE + t * 15 + 1 + m];
    }
    __syncthreads();
    if (threadIdx.x == 0) {
        int nv = 0;
        while (nv < MAXOBJ && sg[nv][0] != 0.0f) nv++;
        s_nv = nv;
    }
    __syncthreads();

    if (c >= NPIX) return;
    int nv = s_nv;
    int best = -1;
    for (int t = 0; t < nv; t++) {
        int gi = (int)floorf(sg[t][0] * 19.0f);
        int gj = (int)floorf(sg[t][1] * 19.0f);
        if (gj * NW + gi == c) best = t;
    }
    int cellIdx = b * NPIX + c;
    g_flag[cellIdx] = (best >= 0) ? 1u : 0u;
    if (best < 0) return;

    float g0 = sg[best][0], g1 = sg[best][1];
    float gi = floorf(g0 * 19.0f), gj = floorf(g1 * 19.0f);
    float tv[12];
    tv[0] = g0 * 19.0f - gi;
    tv[1] = g1 * 19.0f - gj;
    #pragma unroll
    for (int k = 1; k < 6; k++) {
        tv[2 * k]     = (sg[best][2 * k]     - g0) * 19.0f;
        tv[2 * k + 1] = (sg[best][2 * k + 1] - g1) * 19.0f;
    }
    #pragma unroll
    for (int m = 0; m < 12; m++) g_tvals[cellIdx * 12 + m] = tv[m];
    g_tcls[cellIdx] = (int)tgt[b * TSTRIDE + best * 15];

    // tconf = confs[b, best, anchor 0 @ pixel c]
    int j = c / NW, i = c - j * NW;
    const float* base = out + (size_t)b * TOTCH * NPIX + c;   // anchor 0
    float v[12];
    #pragma unroll
    for (int k = 0; k < 12; k++) v[k] = base[(size_t)k * NPIX];
    float px0 = (sigmoidf_(v[0]) + (float)i) * (640.0f / 19.0f);
    float py0 = (sigmoidf_(v[1]) + (float)j) * (480.0f / 19.0f);
    float s6 = 0.0f;
    #pragma unroll
    for (int m = 0; m < 6; m++) {
        float pcx = (m == 0) ? px0 : fmaf(v[2 * m],     640.0f / 19.0f, px0);
        float pcy = (m == 0) ? py0 : fmaf(v[2 * m + 1], 480.0f / 19.0f, py0);
        float dx = sg[best][2 * m]     * 640.0f - pcx;
        float dy = sg[best][2 * m + 1] * 480.0f - pcy;
        float d2 = fmaf(dx, dx, dy * dy);
        if (d2 < 6400.0f)
            s6 += __expf(fmaf(sqrtf(d2), -0.025f, 2.0f)) - 1.0f;
    }
    g_tconf[cellIdx] = s6 * INV6CONF0;
}

// -------------------------------------------------------------------------
// Hot kernel: per (b, anchor) compute cur_conf = max_t confs[b,t,a],
// then fused conf-loss contribution. grid=(8, nB), 256 threads.
// -------------------------------------------------------------------------
__global__ void k_main(const float* __restrict__ out, const float* __restrict__ tgt) {
    int b = blockIdx.y;
    __shared__ float sgx[MAXOBJ * 6];
    __shared__ float sgy[MAXOBJ * 6];
    __shared__ int s_nv;

    for (int idx = threadIdx.x; idx < MAXOBJ * 6; idx += blockDim.x) {
        int t = idx / 6, m = idx - t * 6;
        sgx[idx] = tgt[b * TSTRIDE + t * 15 + 1 + 2 * m] * 640.0f;
        sgy[idx] = tgt[b * TSTRIDE + t * 15 + 2 + 2 * m] * 480.0f;
    }
    if (threadIdx.x == 0) {
        int nv = 0;
        while (nv < MAXOBJ && tgt[b * TSTRIDE + nv * 15 + 1] != 0.0f) nv++;
        s_nv = nv;
    }
    __syncthreads();

    float contrib = 0.0f;
    int aflat = blockIdx.x * blockDim.x + threadIdx.x;
    if (aflat < NANCH) {
        int a = aflat / NPIX, pix = aflat - a * NPIX;
        int j = pix / NW, i = pix - j * NW;
        const float* base = out + ((size_t)b * TOTCH + a * NCH) * NPIX + pix;
        float v[13];
        #pragma unroll
        for (int k = 0; k < 13; k++) v[k] = base[(size_t)k * NPIX];

        float pcx[6], pcy[6];
        pcx[0] = (sigmoidf_(v[0]) + (float)i) * (640.0f / 19.0f);
        pcy[0] = (sigmoidf_(v[1]) + (float)j) * (480.0f / 19.0f);
        #pragma unroll
        for (int m = 1; m < 6; m++) {
            pcx[m] = fmaf(v[2 * m],     640.0f / 19.0f, pcx[0]);
            pcy[m] = fmaf(v[2 * m + 1], 480.0f / 19.0f, pcy[0]);
        }

        float cmax = 0.0f;
        int nv = s_nv;
        for (int t = 0; t < nv; t++) {
            float s = 0.0f;
            #pragma unroll
            for (int m = 0; m < 6; m++) {
                float dx = sgx[t * 6 + m] - pcx[m];
                float dy = sgy[t * 6 + m] - pcy[m];
                float d2 = fmaf(dx, dx, dy * dy);
                if (d2 < 6400.0f)
                    s += __expf(fmaf(sqrtf(d2), -0.025f, 2.0f)) - 1.0f;
            }
            cmax = fmaxf(cmax, s);
        }
        float cur  = cmax * INV6CONF0;
        float conf = sigmoidf_(v[12]);
        int cellIdx = b * NPIX + pix;
        float mask, tc;
        if (a == 0 && g_flag[cellIdx]) { mask = 5.0f; tc = g_tconf[cellIdx]; }
        else                           { mask = (cur < 0.4f) ? 1.0f : 0.0f; tc = 0.0f; }
        float d = conf - tc;
        contrib = 0.5f * mask * d * d;
    }
    block_reduce_add(contrib);
}

// -------------------------------------------------------------------------
// Coord + class loss at assigned cells (anchor 0 only). grid=nB, 384 threads.
// -------------------------------------------------------------------------
__global__ void k_coordcls(const float* __restrict__ out) {
    int b = blockIdx.x;
    int c = threadIdx.x;
    float contrib = 0.0f;
    if (c < NPIX && g_flag[b * NPIX + c]) {
        int cellIdx = b * NPIX + c;
        const float* base = out + (size_t)b * TOTCH * NPIX + c;  // anchor 0
        float lc = 0.0f;
        #pragma unroll
        for (int k = 0; k < 12; k++) {
            float p = base[(size_t)k * NPIX];
            if (k < 2) p = sigmoidf_(p);
            float d = p - g_tvals[cellIdx * 12 + k];
            lc = fmaf(d, d, lc);
        }
        contrib = 0.5f * lc;                 // COORD_SCALE = 1

        float l[13], mx = -1e30f;
        #pragma unroll
        for (int k = 0; k < 13; k++) {
            l[k] = base[(size_t)(13 + k) * NPIX];
            mx = fmaxf(mx, l[k]);
        }
        float se = 0.0f;
        #pragma unroll
        for (int k = 0; k < 13; k++) se += __expf(l[k] - mx);
        float lse = mx + logf(se);
        contrib += lse - l[g_tcls[cellIdx]]; // CLASS_SCALE = 1
    }
    block_reduce_add(contrib);
}

__global__ void k_fin(float* out) { out[0] = (float)g_acc; }

extern "C" void kernel_launch(void* const* d_in, const int* in_sizes, int n_in,
                              void* d_out, int out_size) {
    const float* output = (const float*)d_in[0];
    const float* target = (const float*)d_in[1];
    int nB = in_sizes[1] / TSTRIDE;
    if (nB > MAXB) nB = MAXB;

    k_zero<<<1, 1>>>();
    k_assign<<<nB, 384>>>(output, target);
    k_main<<<dim3((NANCH + 255) / 256, nB), 256>>>(output, target);
    k_coordcls<<<nB, 384>>>(output);
    k_fin<<<1, 1>>>((float*)d_out);
}

// round 12
// speedup vs baseline: 1.1790x; 1.1790x over previous
#include <cuda_runtime.h>
#include <math.h>

#define NW    19
#define NH    19
#define NPIX  361          // 19*19
#define NA_   5
#define NCH   26           // 13 + NC
#define TOTCH 130          // NA_*NCH
#define MAXB  64
#define MAXOBJ 50
#define NANCH (NA_*NPIX)   // 1805
#define TSTRIDE 750        // MAXOBJ*15
#define TPB_MAIN 128
#define BLKX_MAIN ((NANCH + TPB_MAIN - 1) / TPB_MAIN)   // 15

// 1/(6*(e^2-1))
#define INV6CONF0 0.026086274f

// scratch (no allocations allowed)
__device__ double        g_acc;
__device__ float         g_tconf[MAXB * NPIX];
__device__ float         g_tvals[MAXB * NPIX * 12];
__device__ int           g_tcls [MAXB * NPIX];
__device__ unsigned char g_flag [MAXB * NPIX];
__device__ float2        g_sc   [MAXB * MAXOBJ * 6];   // corners pre-scaled to pixels
__device__ int           g_nv   [MAXB];

__device__ __forceinline__ float sigmoidf_(float x) {
    return 1.0f / (1.0f + __expf(-x));
}

// -------------------------------------------------------------------------
// Setup kernel: per-cell gather of the scatter-with-overwrite scan
// (last valid object whose cell matches wins), tvals/tcls/tconf for assigned
// cells, packed+scaled corner cache, and accumulator reset.
// grid = nB blocks, 384 threads.
// -------------------------------------------------------------------------
__global__ void k_assign(const float* __restrict__ out, const float* __restrict__ tgt) {
    int b = blockIdx.x;
    int c = threadIdx.x;
    __shared__ float sg[MAXOBJ][12];
    __shared__ int s_nv;

    if (b == 0 && c == 0) g_acc = 0.0;

    for (int idx = threadIdx.x; idx < MAXOBJ * 12; idx += blockDim.x) {
        int t = idx / 12, m = idx - t * 12;
        sg[t][m] = tgt[b * TSTRIDE + t * 15 + 1 + m];
    }
    __syncthreads();
    if (threadIdx.x == 0) {
        int nv = 0;
        while (nv < MAXOBJ && sg[nv][0] != 0.0f) nv++;
        s_nv = nv;
        g_nv[b] = nv;
    }
    __syncthreads();

    // packed, pre-scaled corner cache for the hot kernel
    for (int idx = threadIdx.x; idx < MAXOBJ * 6; idx += blockDim.x) {
        int t = idx / 6, m = idx - t * 6;
        g_sc[b * MAXOBJ * 6 + idx] =
            make_float2(sg[t][2 * m] * 640.0f, sg[t][2 * m + 1] * 480.0f);
    }

    if (c >= NPIX) return;
    int nv = s_nv;
    int best = -1;
    for (int t = 0; t < nv; t++) {
        int gi = (int)floorf(sg[t][0] * 19.0f);
        int gj = (int)floorf(sg[t][1] * 19.0f);
        if (gj * NW + gi == c) best = t;
    }
    int cellIdx = b * NPIX + c;
    g_flag[cellIdx] = (best >= 0) ? 1u : 0u;
    if (best < 0) return;

    float g0 = sg[best][0], g1 = sg[best][1];
    float gi = floorf(g0 * 19.0f), gj = floorf(g1 * 19.0f);
    float tv[12];
    tv[0] = g0 * 19.0f - gi;
    tv[1] = g1 * 19.0f - gj;
    #pragma unroll
    for (int k = 1; k < 6; k++) {
        tv[2 * k]     = (sg[best][2 * k]     - g0) * 19.0f;
        tv[2 * k + 1] = (sg[best][2 * k + 1] - g1) * 19.0f;
    }
    #pragma unroll
    for (int m = 0; m < 12; m++) g_tvals[cellIdx * 12 + m] = tv[m];
    g_tcls[cellIdx] = (int)tgt[b * TSTRIDE + best * 15];

    // tconf = confs[b, best, anchor 0 @ pixel c]
    int j = c / NW, i = c - j * NW;
    const float* base = out + (size_t)b * TOTCH * NPIX + c;   // anchor 0
    float v[12];
    #pragma unroll
    for (int k = 0; k < 12; k++) v[k] = base[(size_t)k * NPIX];
    float px0 = (sigmoidf_(v[0]) + (float)i) * (640.0f / 19.0f);
    float py0 = (sigmoidf_(v[1]) + (float)j) * (480.0f / 19.0f);
    float s6 = 0.0f;
    #pragma unroll
    for (int m = 0; m < 6; m++) {
        float pcx = (m == 0) ? px0 : fmaf(v[2 * m],     640.0f / 19.0f, px0);
        float pcy = (m == 0) ? py0 : fmaf(v[2 * m + 1], 480.0f / 19.0f, py0);
        float dx = sg[best][2 * m]     * 640.0f - pcx;
        float dy = sg[best][2 * m + 1] * 480.0f - pcy;
        float d2 = fmaf(dx, dx, dy * dy);
        if (d2 < 6400.0f)
            s6 += __expf(fmaf(sqrtf(d2), -0.025f, 2.0f)) - 1.0f;
    }
    g_tconf[cellIdx] = s6 * INV6CONF0;
}

// -------------------------------------------------------------------------
// Fused hot kernel: conf loss for every (b, anchor), coord+cls loss for
// assigned anchor-0 cells. grid = (15, nB), 128 threads.
// -------------------------------------------------------------------------
__global__ void k_fused(const float* __restrict__ out) {
    int b = blockIdx.y;
    __shared__ float2 sc[MAXOBJ * 6];
    __shared__ int s_nv;
    __shared__ float ws[TPB_MAIN / 32];

    for (int idx = threadIdx.x; idx < MAXOBJ * 6; idx += TPB_MAIN)
        sc[idx] = g_sc[b * MAXOBJ * 6 + idx];
    if (threadIdx.x == 0) s_nv = g_nv[b];
    __syncthreads();

    float contrib = 0.0f;
    int aflat = blockIdx.x * TPB_MAIN + threadIdx.x;
    if (aflat < NANCH) {
        int a = aflat / NPIX, pix = aflat - a * NPIX;
        int j = pix / NW, i = pix - j * NW;
        const float* base = out + ((size_t)b * TOTCH + a * NCH) * NPIX + pix;
        float v[13];
        #pragma unroll
        for (int k = 0; k < 13; k++) v[k] = base[(size_t)k * NPIX];

        float pcx[6], pcy[6];
        pcx[0] = (sigmoidf_(v[0]) + (float)i) * (640.0f / 19.0f);
        pcy[0] = (sigmoidf_(v[1]) + (float)j) * (480.0f / 19.0f);
        #pragma unroll
        for (int m = 1; m < 6; m++) {
            pcx[m] = fmaf(v[2 * m],     640.0f / 19.0f, pcx[0]);
            pcy[m] = fmaf(v[2 * m + 1], 480.0f / 19.0f, pcy[0]);
        }

        float cmax = 0.0f;
        int nv = s_nv;
        for (int t = 0; t < nv; t++) {
            float d2[6];
            #pragma unroll
            for (int m = 0; m < 6; m++) {
                float2 s2 = sc[t * 6 + m];
                float dx = s2.x - pcx[m];
                float dy = s2.y - pcy[m];
                d2[m] = fmaf(dx, dx, dy * dy);
            }
            float dmin = d2[0];
            #pragma unroll
            for (int m = 1; m < 6; m++) dmin = fminf(dmin, d2[m]);
            if (dmin < 6400.0f) {   // skip MUFU burst when no corner is close
                float s = 0.0f;
                #pragma unroll
                for (int m = 0; m < 6; m++) {
                    if (d2[m] < 6400.0f)
                        s += __expf(fmaf(sqrtf(d2[m]), -0.025f, 2.0f)) - 1.0f;
                }
                cmax = fmaxf(cmax, s);
            }
        }
        float cur  = cmax * INV6CONF0;
        float conf = sigmoidf_(v[12]);
        int cellIdx = b * NPIX + pix;
        bool assigned = (a == 0) && g_flag[cellIdx];
        float mask, tc;
        if (assigned) { mask = 5.0f; tc = g_tconf[cellIdx]; }
        else          { mask = (cur < 0.4f) ? 1.0f : 0.0f; tc = 0.0f; }
        float d = conf - tc;
        contrib = 0.5f * mask * d * d;

        // fused coord + class loss (anchor 0, assigned cells only)
        if (assigned) {
            float lc = 0.0f;
            #pragma unroll
            for (int k = 0; k < 12; k++) {
                float p = v[k];
                if (k < 2) p = sigmoidf_(p);
                float dd = p - g_tvals[cellIdx * 12 + k];
                lc = fmaf(dd, dd, lc);
            }
            contrib += 0.5f * lc;            // COORD_SCALE = 1

            float l[13], mx = -1e30f;
            #pragma unroll
            for (int k = 0; k < 13; k++) {
                l[k] = base[(size_t)(13 + k) * NPIX];
                mx = fmaxf(mx, l[k]);
            }
            float se = 0.0f;
            #pragma unroll
            for (int k = 0; k < 13; k++) se += __expf(l[k] - mx);
            float lse = mx + logf(se);
            contrib += lse - l[g_tcls[cellIdx]];  // CLASS_SCALE = 1
        }
    }

    // block reduction into global double accumulator
    float vsum = contrib;
    #pragma unroll
    for (int o = 16; o > 0; o >>= 1) vsum += __shfl_down_sync(0xffffffffu, vsum, o);
    int lane = threadIdx.x & 31, w = threadIdx.x >> 5;
    if (lane == 0) ws[w] = vsum;
    __syncthreads();
    if (w == 0) {
        float x = (lane < TPB_MAIN / 32) ? ws[lane] : 0.0f;
        #pragma unroll
        for (int o = 16; o > 0; o >>= 1) x += __shfl_down_sync(0xffffffffu, x, o);
        if (lane == 0) atomicAdd(&g_acc, (double)x);
    }
}

__global__ void k_fin(float* out) { out[0] = (float)g_acc; }

extern "C" void kernel_launch(void* const* d_in, const int* in_sizes, int n_in,
                              void* d_out, int out_size) {
    const float* output = (const float*)d_in[0];
    const float* target = (const float*)d_in[1];
    int nB = in_sizes[1] / TSTRIDE;
    if (nB > MAXB) nB = MAXB;

    k_assign<<<nB, 384>>>(output, target);
    k_fused<<<dim3(BLKX_MAIN, nB), TPB_MAIN>>>(output);
    k_fin<<<1, 1>>>((float*)d_out);
}